// round 2
// baseline (speedup 1.0000x reference)
#include <cuda_runtime.h>

#define FN   262144
#define FNC  4096
#define FD   5
#define FK   4
#define W_JAC (2.0f/3.0f)

// Scratch (static device globals; no runtime allocation allowed)
__device__ float g_Ac[FNC * FNC];     // dense coarse operator, 64 MB
__device__ float g_diag_c[FNC];
__device__ float g_bc[FNC];
__device__ float g_xc[2 * FNC];
__device__ float g_xbuf[2 * FN];

// ---------------------------------------------------------------------------
__global__ void k_zero_Ac() {
    float4 z = make_float4(0.f, 0.f, 0.f, 0.f);
    float4* p = reinterpret_cast<float4*>(g_Ac);
    int total = FNC * FNC / 4;
    for (int i = blockIdx.x * blockDim.x + threadIdx.x; i < total;
         i += gridDim.x * blockDim.x)
        p[i] = z;
}

// RAP: one thread per (row i, nonzero j). 16 atomics each.
__global__ void k_rap(const float* __restrict__ Av, const int* __restrict__ Acl,
                      const float* __restrict__ Pv, const int* __restrict__ Pc) {
    int t = blockIdx.x * blockDim.x + threadIdx.x;
    if (t >= FN * FD) return;
    int i = t / FD;
    int j = t - i * FD;
    int cj = __ldg(&Acl[i * FD + j]);
    float a = __ldg(&Av[i * FD + j]);
    float pa[FK]; int ia[FK];
    float qb[FK]; int ib[FK];
#pragma unroll
    for (int k = 0; k < FK; k++) {
        pa[k] = __ldg(&Pv[i * FK + k]) * a;
        ia[k] = __ldg(&Pc[i * FK + k]);
        qb[k] = __ldg(&Pv[cj * FK + k]);
        ib[k] = __ldg(&Pc[cj * FK + k]);
    }
#pragma unroll
    for (int ka = 0; ka < FK; ka++) {
        int base = ia[ka] * FNC;
#pragma unroll
        for (int kb = 0; kb < FK; kb++)
            atomicAdd(&g_Ac[base + ib[kb]], pa[ka] * qb[kb]);
    }
}

__global__ void k_diagc() {
    int c = blockIdx.x * blockDim.x + threadIdx.x;
    if (c < FNC) g_diag_c[c] = g_Ac[c * FNC + c];
}

__global__ void k_zero_bc() {
    int c = blockIdx.x * blockDim.x + threadIdx.x;
    if (c < FNC) g_bc[c] = 0.f;
}

// One weighted-Jacobi sweep on the fine ELL system: xout = xin + W*(b - A xin)/diag
__global__ void k_smooth(const float* __restrict__ xin, float* __restrict__ xout,
                         const float* __restrict__ b, const float* __restrict__ Av,
                         const int* __restrict__ Acl) {
    int i = blockIdx.x * blockDim.x + threadIdx.x;
    if (i >= FN) return;
    float diag = __ldg(&Av[i * FD]);
    float s = 0.f;
#pragma unroll
    for (int j = 0; j < FD; j++)
        s += __ldg(&Av[i * FD + j]) * __ldg(&xin[__ldg(&Acl[i * FD + j])]);
    xout[i] = xin[i] + W_JAC * (b[i] - s) / diag;
}

// residual + restriction: bc += P^T (b - A x)
__global__ void k_resid_bc(const float* __restrict__ xin, const float* __restrict__ b,
                           const float* __restrict__ Av, const int* __restrict__ Acl,
                           const float* __restrict__ Pv, const int* __restrict__ Pc) {
    int i = blockIdx.x * blockDim.x + threadIdx.x;
    if (i >= FN) return;
    float s = 0.f;
#pragma unroll
    for (int j = 0; j < FD; j++)
        s += __ldg(&Av[i * FD + j]) * __ldg(&xin[__ldg(&Acl[i * FD + j])]);
    float r = b[i] - s;
#pragma unroll
    for (int k = 0; k < FK; k++)
        atomicAdd(&g_bc[__ldg(&Pc[i * FK + k])], __ldg(&Pv[i * FK + k]) * r);
}

// First coarse Jacobi sweep from xc=0:  xc = W * bc / diag_c
__global__ void k_cfirst(float* __restrict__ xc) {
    int c = blockIdx.x * blockDim.x + threadIdx.x;
    if (c < FNC) xc[c] = W_JAC * g_bc[c] / g_diag_c[c];
}

// One coarse Jacobi sweep with dense Ac: warp-per-row, float4 loads
__global__ void k_citer(const float* __restrict__ xin, float* __restrict__ xout) {
    int gw = (blockIdx.x * blockDim.x + threadIdx.x) >> 5;
    int lane = threadIdx.x & 31;
    if (gw >= FNC) return;
    const float4* row = reinterpret_cast<const float4*>(g_Ac + (size_t)gw * FNC);
    const float4* xv = reinterpret_cast<const float4*>(xin);
    float s = 0.f;
#pragma unroll 4
    for (int j = lane; j < FNC / 4; j += 32) {
        float4 a = row[j];
        float4 x4 = xv[j];
        s += a.x * x4.x + a.y * x4.y + a.z * x4.z + a.w * x4.w;
    }
#pragma unroll
    for (int o = 16; o; o >>= 1) s += __shfl_xor_sync(0xffffffffu, s, o);
    if (lane == 0)
        xout[gw] = xin[gw] + W_JAC * (g_bc[gw] - s) / g_diag_c[gw];
}

// coarse correction: xout = xin + P xc
__global__ void k_prolong(const float* __restrict__ xin, float* __restrict__ xout,
                          const float* __restrict__ Pv, const int* __restrict__ Pc,
                          const float* __restrict__ xc) {
    int i = blockIdx.x * blockDim.x + threadIdx.x;
    if (i >= FN) return;
    float s = 0.f;
#pragma unroll
    for (int k = 0; k < FK; k++)
        s += __ldg(&Pv[i * FK + k]) * __ldg(&xc[__ldg(&Pc[i * FK + k])]);
    xout[i] = xin[i] + s;
}

// ---------------------------------------------------------------------------
extern "C" void kernel_launch(void* const* d_in, const int* in_sizes, int n_in,
                              void* d_out, int out_size) {
    const float* b   = (const float*)d_in[0];
    const float* x0  = (const float*)d_in[1];
    const float* Av  = (const float*)d_in[2];
    const float* Pv  = (const float*)d_in[3];
    const int*   Acl = (const int*)d_in[4];
    const int*   Pc  = (const int*)d_in[5];
    float* out = (float*)d_out;

    float *xbuf, *xc, *xcbase;
    cudaGetSymbolAddress((void**)&xbuf, g_xbuf);
    cudaGetSymbolAddress((void**)&xcbase, g_xc);
    float* bufs[2] = { xbuf, xbuf + FN };
    float* xc0 = xcbase;
    float* xc1 = xcbase + FNC;

    const int BT = 256;
    const int GB_N = (FN + BT - 1) / BT;          // 1024 blocks for fine kernels
    const int GB_NC = (FNC + BT - 1) / BT;        // 16 blocks for coarse vec ops
    const int GB_CITER = (FNC * 32 + BT - 1) / BT; // warp-per-row: 512 blocks

    // Setup: Ac = P^T A P, diag_c
    k_zero_Ac<<<4096, BT>>>();
    k_rap<<<(FN * FD + BT - 1) / BT, BT>>>(Av, Acl, Pv, Pc);
    k_diagc<<<GB_NC, BT>>>();

    const float* cur = x0;
    int nb = 0;
    for (int cyc = 0; cyc < 2; ++cyc) {
        // pre-smooth x3
        for (int s = 0; s < 3; ++s) {
            k_smooth<<<GB_N, BT>>>(cur, bufs[nb], b, Av, Acl);
            cur = bufs[nb];
            nb ^= 1;
        }
        // restriction
        k_zero_bc<<<GB_NC, BT>>>();
        k_resid_bc<<<GB_N, BT>>>(cur, b, Av, Acl, Pv, Pc);
        // coarse solve: 10 weighted-Jacobi sweeps (first is closed-form)
        k_cfirst<<<GB_NC, BT>>>(xc0);
        float* ci = xc0;
        float* co = xc1;
        for (int t = 0; t < 9; ++t) {
            k_citer<<<GB_CITER, BT>>>(ci, co);
            float* tmp = ci; ci = co; co = tmp;
        }
        // prolongation / correction
        k_prolong<<<GB_N, BT>>>(cur, bufs[nb], Pv, Pc, ci);
        cur = bufs[nb];
        nb ^= 1;
        // post-smooth x3 (last sweep of last cycle writes d_out)
        for (int s = 0; s < 3; ++s) {
            float* dst = (cyc == 1 && s == 2) ? out : bufs[nb];
            k_smooth<<<GB_N, BT>>>(cur, dst, b, Av, Acl);
            cur = dst;
            nb ^= 1;
        }
    }
}